// round 16
// baseline (speedup 1.0000x reference)
#include <cuda_runtime.h>
#include <cuda_fp16.h>

#define NN    20000
#define MPAD  20096                 /* buffer sizing only */
#define DIN   768
#define NREL  8
#define NE    320000
#define NSEG  (NN * NREL)
#define KMEAN (NREL * DIN)          /* 6144 */
#define KTOT  (KMEAN + DIN)         /* 6912 */
#define NSTG  (KTOT / 64)           /* 108 K-stages of 64; 108 % 3 == 0 */
#define NTILE_N 6                   /* 768 / 128 */
#define NTILE_M 157                 /* ceil(20000/128) */
#define NTILES  (NTILE_N * NTILE_M) /* 942 */
#define NPERS   296                 /* 2 CTAs x 148 SMs */

/* ------------------------------------------------------------------ */
/* static device scratch                                              */
/* ------------------------------------------------------------------ */
__device__ __half g_meanH[(size_t)MPAD * KMEAN];            /* 247 MB */
__device__ __half g_tailH[2][(size_t)MPAD * DIN];           /* [0]=x, [1]=h */
__device__ __half g_BH[2][(size_t)DIN * KTOT];              /* B^T per layer */
__device__ int    g_sorted_src[NE];
__device__ int    g_eseg[NE];                               /* decoded edge cache */
__device__ int    g_esrc[NE];
__device__ int    g_seg_cnt[NSEG];
__device__ int    g_seg_off[NSEG];                          /* partial (per-block) */
__device__ int    g_cursor[NSEG];
__device__ int    g_blk[640];
__device__ int    g_blkpre[640];
__device__ int    g_ticket[2];
__device__ int    g_is64;

/* ------------------------------------------------------------------ */
/* PTX helpers — all non-arch-specific (sm_80+ class)                 */
/* ------------------------------------------------------------------ */
__device__ __forceinline__ unsigned smem_u32(const void* p) {
    unsigned a;
    asm("{ .reg .u64 t; cvta.to.shared.u64 t, %1; cvt.u32.u64 %0, t; }" : "=r"(a) : "l"(p));
    return a;
}
#define CP16(dst, src) \
    asm volatile("cp.async.cg.shared.global [%0], [%1], 16;" :: "r"(dst), "l"(src))
#define CP_COMMIT() asm volatile("cp.async.commit_group;" ::: "memory")
#define CP_WAIT(n)  asm volatile("cp.async.wait_group %0;" :: "n"(n) : "memory")

#define LDSM4(R, addr)                                                       \
    asm volatile("ldmatrix.sync.aligned.m8n8.x4.shared.b16 {%0,%1,%2,%3}, [%4];" \
        : "=r"((R)[0]), "=r"((R)[1]), "=r"((R)[2]), "=r"((R)[3]) : "r"(addr))

#define MMA16816F16(C, A, B0, B1)                                            \
    asm volatile("mma.sync.aligned.m16n8k16.row.col.f32.f16.f16.f32 "        \
        "{%0,%1,%2,%3}, {%4,%5,%6,%7}, {%8,%9}, {%0,%1,%2,%3};"              \
        : "+f"((C)[0]), "+f"((C)[1]), "+f"((C)[2]), "+f"((C)[3])             \
        : "r"((A)[0]), "r"((A)[1]), "r"((A)[2]), "r"((A)[3]),                \
          "r"(B0), "r"(B1))

/* SW128 swizzle for 128-byte rows */
__device__ __forceinline__ unsigned swz128(unsigned off) { return off ^ ((off >> 3) & 0x70); }

/* ------------------------------------------------------------------ */
/* CSR build (dtype detect in k_zero; scan3 folded into consumers;    */
/* edge decode cached by k_hist)                                      */
/* ------------------------------------------------------------------ */
__global__ void k_zero(const void* et_raw) {
    int i = blockIdx.x * blockDim.x + threadIdx.x;
    if (i < NSEG) { g_seg_cnt[i] = 0; g_cursor[i] = 0; }
    if (i < 2) g_ticket[i] = 0;
    /* block 0: int64-vs-int32 detection on edge_type words */
    if (blockIdx.x == 0) {
        __shared__ int nz;
        if (threadIdx.x == 0) nz = 0;
        __syncthreads();
        const int* w = (const int*)et_raw;
        int cnt = 0;
        for (int j = threadIdx.x; j < 2048; j += blockDim.x)
            if (w[2 * j + 1] != 0) cnt++;
        atomicAdd(&nz, cnt);
        __syncthreads();
        if (threadIdx.x == 0) g_is64 = (nz == 0) ? 1 : 0;
    }
}

__device__ __forceinline__ void load_edge(const void* ei, const void* et, int e,
                                          int& src, int& dst, int& r) {
    if (g_is64) {
        const long long* p = (const long long*)ei;
        src = (int)p[e]; dst = (int)p[NE + e];
        r = (int)((const long long*)et)[e];
    } else {
        const int* p = (const int*)ei;
        src = p[e]; dst = p[NE + e];
        r = ((const int*)et)[e];
    }
}

/* histogram + decoded-edge cache (k_place reuses the decode) */
__global__ void k_hist(const void* ei, const void* et) {
    int e = blockIdx.x * blockDim.x + threadIdx.x;
    if (e >= NE) return;
    int s, d, r; load_edge(ei, et, e, s, d, r);
    int seg = d * NREL + r;
    g_eseg[e] = seg;
    g_esrc[e] = s;
    atomicAdd(&g_seg_cnt[seg], 1);
}

/* per-block exclusive scan; block totals to g_blk */
__global__ void k_scan1() {
    __shared__ int ws[8];
    int i = blockIdx.x * 256 + threadIdx.x;
    int lane = threadIdx.x & 31, w = threadIdx.x >> 5;
    int v = g_seg_cnt[i];
    int s = v;
#pragma unroll
    for (int d = 1; d < 32; d <<= 1) {
        int t = __shfl_up_sync(0xffffffffu, s, d);
        if (lane >= d) s += t;
    }
    if (lane == 31) ws[w] = s;
    __syncthreads();
    if (w == 0) {
        int val = (lane < 8) ? ws[lane] : 0;
        int sc = val;
#pragma unroll
        for (int d = 1; d < 8; d <<= 1) {
            int t = __shfl_up_sync(0xffffffffu, sc, d);
            if (lane >= d) sc += t;
        }
        if (lane < 8) ws[lane] = sc - val;
    }
    __syncthreads();
    int excl = s - v + ws[w];
    g_seg_off[i] = excl;                       /* partial: block-local */
    if (threadIdx.x == 255) g_blk[blockIdx.x] = excl + v;
}
__global__ void k_scan2() {
    __shared__ int sh[1024];
    int t = threadIdx.x;
    int v = (t < 625) ? g_blk[t] : 0;
    sh[t] = v;
    __syncthreads();
    for (int d = 1; d < 1024; d <<= 1) {
        int u = (t >= d) ? sh[t - d] : 0;
        __syncthreads();
        sh[t] += u;
        __syncthreads();
    }
    if (t < 625) g_blkpre[t] = sh[t] - v;
}

__global__ void k_place() {
    int e = blockIdx.x * blockDim.x + threadIdx.x;
    if (e >= NE) return;
    int seg = g_eseg[e];
    int base = g_seg_off[seg] + g_blkpre[seg >> 8];   /* scan3 folded in */
    g_sorted_src[base + atomicAdd(&g_cursor[seg], 1)] = g_esrc[e];
}

/* ------------------------------------------------------------------ */
/* operand preparation                                                */
/* ------------------------------------------------------------------ */
__global__ void k_convW(const float* __restrict__ W1, const float* __restrict__ root1,
                        __half* __restrict__ bh1,
                        const float* __restrict__ W2, const float* __restrict__ root2,
                        __half* __restrict__ bh2) {
    __shared__ float t[32][33];
    const float* W    = blockIdx.z ? W2 : W1;
    const float* root = blockIdx.z ? root2 : root1;
    __half* bh        = blockIdx.z ? bh2 : bh1;
    int tx = threadIdx.x, ty = threadIdx.y;
    int kb = blockIdx.x * 32, nb = blockIdx.y * 32;
    for (int j = ty; j < 32; j += 8) {
        int k = kb + j;
        const float* src = (k < KMEAN) ? (W + (size_t)k * DIN)
                                       : (root + (size_t)(k - KMEAN) * DIN);
        t[j][tx] = src[nb + tx];
    }
    __syncthreads();
    for (int j = ty; j < 32; j += 8) {
        int n = nb + j;
        bh[(size_t)n * KTOT + kb + tx] = __float2half_rn(t[tx][j]);
    }
}

__global__ void k_convX(const float* __restrict__ x, __half* __restrict__ h) {
    int idx = blockIdx.x * blockDim.x + threadIdx.x;
    if (idx >= NN * (DIN / 4)) return;
    float4 v = ((const float4*)x)[idx];
    __half2 a = __floats2half2_rn(v.x, v.y);
    __half2 b = __floats2half2_rn(v.z, v.w);
    ((__half2*)h)[idx * 2 + 0] = a;
    ((__half2*)h)[idx * 2 + 1] = b;
}

/* segment mean over fp16 rows -> fp16 mean region (fp32 accum).      */
/* meanH written with streaming hint (write-once 247 MB stream).      */
__global__ void k_aggregate(const __half* __restrict__ xin) {
    int gw = (blockIdx.x * blockDim.x + threadIdx.x) >> 5;
    if (gw >= NSEG) return;
    int lane = threadIdx.x & 31;
    int off = g_seg_off[gw] + g_blkpre[gw >> 8];   /* scan3 folded in */
    int cnt = g_seg_cnt[gw];

    float acc[24];
#pragma unroll
    for (int j = 0; j < 24; j++) acc[j] = 0.f;

    for (int e = 0; e < cnt; e++) {
        const uint4* row = (const uint4*)(xin + (size_t)g_sorted_src[off + e] * DIN);
#pragma unroll
        for (int j = 0; j < 3; j++) {
            uint4 v = row[j * 32 + lane];
            const __half2* h2 = (const __half2*)&v;
#pragma unroll
            for (int q = 0; q < 4; q++) {
                float2 f = __half22float2(h2[q]);
                acc[j * 8 + q * 2 + 0] += f.x;
                acc[j * 8 + q * 2 + 1] += f.y;
            }
        }
    }
    float inv = 1.0f / fmaxf((float)cnt, 1.0f);
    uint4* mh = (uint4*)(g_meanH + (size_t)gw * DIN);   /* gw*768 == dst*6144 + r*768 */
#pragma unroll
    for (int j = 0; j < 3; j++) {
        uint4 o;
        __half2* h2 = (__half2*)&o;
#pragma unroll
        for (int q = 0; q < 4; q++)
            h2[q] = __floats2half2_rn(acc[j * 8 + q * 2] * inv,
                                      acc[j * 8 + q * 2 + 1] * inv);
        __stcs(&mh[j * 32 + lane], o);          /* evict-first streaming store */
    }
}

/* ------------------------------------------------------------------ */
/* single-product fp16 GEMM via mma.sync — PERSISTENT CTAs with       */
/* INTER-TILE PIPELINING: tile t+1 is claimed at the top of tile t's  */
/* mainloop, and its stages 0/1 are issued in the loop slots where    */
/* s+2 >= NSTG (iterations 106/107).  Since NSTG % 3 == 0, buffer     */
/* rotation is tile-invariant (stage s <-> buffer s%3), so the next   */
/* tile's mainloop continues the pipeline with zero cold restart and  */
/* the epilogue overlaps the next tile's loads.                       */
/* ------------------------------------------------------------------ */
#define STG_SZ   32768                      /* A 16K + B 16K */
#define OFF_A(b) ((b) * STG_SZ + 0)
#define OFF_B(b) ((b) * STG_SZ + 16384)
#define SMEM_TOTAL (3 * STG_SZ)             /* 98304 */

__global__ __launch_bounds__(256, 2)
void k_gemm_mma(const __half* __restrict__ meanH, const __half* __restrict__ tailH,
                const __half* __restrict__ BH,
                const float* __restrict__ bias, float* __restrict__ outF,
                __half* __restrict__ auxH,
                int do_relu, int write_f32, int write_f16, int ticket_id) {
    extern __shared__ __align__(1024) char smem[];
    __shared__ int s_next;
    const int tid  = threadIdx.x;
    const int wid  = tid >> 5, lane = tid & 31;
    const int wm   = wid >> 2;          /* 0..1 : warp M tile (64 rows) */
    const int wn   = wid & 3;           /* 0..3 : warp N tile (32 cols) */
    const unsigned sbase = smem_u32(smem);
    const int lrow = lane & 15, lcol = lane >> 4;

    /* ---- stage loader: 8 cp.async(16B) per thread per stage ---- */
    auto issue_stage = [&](int s, int buf, int m0, int n0) {
        const int kc = s * 64;
        const __half* ah;
        size_t stride; int c0;
        if (kc < KMEAN) { ah = meanH; stride = KMEAN; c0 = kc; }
        else            { ah = tailH; stride = DIN;   c0 = kc - KMEAN; }
        /* A: 128 rows x 8 chunks of 16B */
#pragma unroll
        for (int t = 0; t < 4; t++) {
            int c   = tid + t * 256;             /* 0..1023 */
            int row = c >> 3, kg = c & 7;
            unsigned sw = swz128((unsigned)(row * 128 + kg * 16));
            int grow = m0 + row; if (grow >= NN) grow = NN - 1;  /* clamp pad rows */
            const char* sa = (const char*)(ah + (size_t)grow * stride + c0) + kg * 16;
            CP16(sbase + OFF_A(buf) + sw, sa);
        }
        /* B: 128 rows x 8 chunks of 16B */
#pragma unroll
        for (int t = 0; t < 4; t++) {
            int c   = tid + t * 256;
            int row = c >> 3, kg = c & 7;
            unsigned sw = swz128((unsigned)(row * 128 + kg * 16));
            const char* sb = (const char*)(BH + (size_t)(n0 + row) * KTOT + kc) + kg * 16;
            CP16(sbase + OFF_B(buf) + sw, sb);
        }
    };

    /* ---- claim first tile + cold prologue ---- */
    if (tid == 0) s_next = atomicAdd(&g_ticket[ticket_id], 1);
    __syncthreads();
    int tile = s_next;
    __syncthreads();                 /* all threads read s_next before overwrite */
    if (tile >= NTILES) return;
    {
        int m0 = (tile / NTILE_N) * 128, n0 = (tile % NTILE_N) * 128;
        issue_stage(0, 0, m0, n0); CP_COMMIT();
        issue_stage(1, 1, m0, n0); CP_COMMIT();
    }

    for (;;) {
        const int n0 = (tile % NTILE_N) * 128;
        const int m0 = (tile / NTILE_N) * 128;

        /* claim the NEXT tile; published to all threads by s=0 barrier */
        if (tid == 0) s_next = atomicAdd(&g_ticket[ticket_id], 1);

        float acc[4][4][4];
#pragma unroll
        for (int a = 0; a < 4; a++)
#pragma unroll
            for (int b = 0; b < 4; b++)
#pragma unroll
                for (int c = 0; c < 4; c++) acc[a][b][c] = 0.f;

        int ntile = NTILES;
        for (int s = 0; s < NSTG; s++) {
            CP_WAIT(1);              /* stage s resident */
            __syncthreads();
            if (s == 0) ntile = s_next;   /* register snapshot after barrier */

            if (s + 2 < NSTG) {
                issue_stage(s + 2, (s + 2) % 3, m0, n0);
            } else if (ntile < NTILES) {
                /* warm the NEXT tile's prologue in the freed buffers */
                int nm0 = (ntile / NTILE_N) * 128, nn0 = (ntile % NTILE_N) * 128;
                issue_stage(s + 2 - NSTG, (s + 2) % 3, nm0, nn0);
            }
            CP_COMMIT();             /* exactly one group per iteration */

            unsigned baseA = sbase + OFF_A(s % 3);
            unsigned baseB = sbase + OFF_B(s % 3);

#pragma unroll
            for (int ks = 0; ks < 4; ks++) {
                unsigned bh[2][4];
#pragma unroll
                for (int p = 0; p < 2; p++) {
                    unsigned off = swz128((unsigned)((wn * 32 + p * 16 + lrow) * 128
                                                     + ks * 32 + lcol * 16));
                    LDSM4(bh[p], baseB + off);
                }
#pragma unroll
                for (int mb = 0; mb < 4; mb++) {
                    unsigned af[4];
                    unsigned off = swz128((unsigned)((wm * 64 + mb * 16 + lrow) * 128
                                                     + ks * 32 + lcol * 16));
                    LDSM4(af, baseA + off);
#pragma unroll
                    for (int nb = 0; nb < 4; nb++) {
                        int p = nb >> 1, q = nb & 1;
                        MMA16816F16(acc[mb][nb], af, bh[p][q], bh[p][q + 2]);
                    }
                }
            }
        }

        /* ---- epilogue: overlaps the next tile's in-flight loads ----
         * fp32 final output: write-once -> streaming store.
         * fp16 aux (h): re-read by next layer's gather -> cached.      */
#pragma unroll
        for (int mb = 0; mb < 4; mb++) {
            int rbase = m0 + wm * 64 + mb * 16 + (lane >> 2);
#pragma unroll
            for (int nb = 0; nb < 4; nb++) {
                int col = n0 + wn * 32 + nb * 8 + (lane & 3) * 2;
                float bv0 = __ldg(&bias[col]);
                float bv1 = __ldg(&bias[col + 1]);
#pragma unroll
                for (int h = 0; h < 2; h++) {
                    int row = rbase + h * 8;
                    float v0 = acc[mb][nb][h * 2 + 0] + bv0;
                    float v1 = acc[mb][nb][h * 2 + 1] + bv1;
                    if (do_relu) { v0 = fmaxf(v0, 0.f); v1 = fmaxf(v1, 0.f); }
                    if (row < NN) {
                        size_t e = (size_t)row * DIN + col;
                        if (write_f32)
                            __stcs((float2*)&outF[e], make_float2(v0, v1));
                        if (write_f16) {
                            __half2 hv = __floats2half2_rn(v0, v1);
                            *(__half2*)(auxH + e) = hv;
                        }
                    }
                }
            }
        }

        tile = ntile;
        if (tile >= NTILES) return;
    }
}

/* ------------------------------------------------------------------ */
extern "C" void kernel_launch(void* const* d_in, const int* in_sizes, int n_in,
                              void* d_out, int out_size) {
    const float* x     = (const float*)d_in[0];
    const void*  ei    = d_in[1];
    const void*  et    = d_in[2];
    const float* W1    = (const float*)d_in[3];
    const float* root1 = (const float*)d_in[4];
    const float* b1    = (const float*)d_in[5];
    const float* W2    = (const float*)d_in[6];
    const float* root2 = (const float*)d_in[7];
    const float* b2    = (const float*)d_in[8];
    float*       out   = (float*)d_out;

    __half *meanH, *tailH, *BH;
    cudaGetSymbolAddress((void**)&meanH, g_meanH);
    cudaGetSymbolAddress((void**)&tailH, g_tailH);
    cudaGetSymbolAddress((void**)&BH, g_BH);
    __half* tail1H = tailH + (size_t)MPAD * DIN;
    __half* B2H    = BH + (size_t)DIN * KTOT;

    cudaFuncSetAttribute(k_gemm_mma, cudaFuncAttributeMaxDynamicSharedMemorySize, SMEM_TOTAL);

    /* CSR build (shared by both layers) */
    k_zero<<<(NSEG + 255) / 256, 256>>>(et);
    k_hist<<<(NE + 255) / 256, 256>>>(ei, et);
    k_scan1<<<NSEG / 256, 256>>>();
    k_scan2<<<1, 1024>>>();
    k_place<<<(NE + 255) / 256, 256>>>();

    /* operand prep (both W conversions in one launch) */
    dim3 wgrid(KTOT / 32, DIN / 32, 2);
    k_convW<<<wgrid, dim3(32, 8)>>>(W1, root1, BH, W2, root2, B2H);
    k_convX<<<(NN * (DIN / 4) + 255) / 256, 256>>>(x, tailH);

    /* layer 1: aggregate fp16 x -> mean; GEMM -> fp16 h only */
    k_aggregate<<<NSEG / 8, 256>>>(tailH);
    k_gemm_mma<<<NPERS, 256, SMEM_TOTAL>>>(meanH, tailH, BH, b1,
                                           nullptr, tail1H, 1, 0, 1, 0);
    /* layer 2: aggregate fp16 h -> mean; GEMM -> fp32 out */
    k_aggregate<<<NSEG / 8, 256>>>(tail1H);
    k_gemm_mma<<<NPERS, 256, SMEM_TOTAL>>>(meanH, tail1H, B2H, b2,
                                           out, nullptr, 0, 1, 0, 1);
}

// round 17
// speedup vs baseline: 1.0826x; 1.0826x over previous
#include <cuda_runtime.h>
#include <cuda_fp16.h>

#define NN    20000
#define MPAD  20096                 /* buffer sizing only */
#define DIN   768
#define NREL  8
#define NE    320000
#define NSEG  (NN * NREL)
#define KMEAN (NREL * DIN)          /* 6144 */
#define KTOT  (KMEAN + DIN)         /* 6912 */
#define NSTG  (KTOT / 64)           /* 108 K-stages of 64 */
#define NTILE_N 6                   /* 768 / 128 */
#define NTILE_M 157                 /* ceil(20000/128) */
#define NTILES  (NTILE_N * NTILE_M) /* 942 */
#define NPERS   296                 /* 2 CTAs x 148 SMs */

/* ------------------------------------------------------------------ */
/* static device scratch                                              */
/* ------------------------------------------------------------------ */
__device__ __half g_meanH[(size_t)MPAD * KMEAN];            /* 247 MB */
__device__ __half g_tailH[2][(size_t)MPAD * DIN];           /* [0]=x, [1]=h */
__device__ __half g_BH[2][(size_t)DIN * KTOT];              /* B^T per layer */
__device__ int    g_sorted_src[NE];
__device__ int    g_eseg[NE];                               /* decoded edge cache */
__device__ int    g_esrc[NE];
__device__ int    g_seg_cnt[NSEG];
__device__ int    g_seg_off[NSEG];                          /* partial (per-block) */
__device__ int    g_cursor[NSEG];
__device__ int    g_blk[640];
__device__ int    g_blkpre[640];
__device__ int    g_ticket[2];
__device__ int    g_is64;

/* ------------------------------------------------------------------ */
/* PTX helpers — all non-arch-specific (sm_80+ class)                 */
/* ------------------------------------------------------------------ */
__device__ __forceinline__ unsigned smem_u32(const void* p) {
    unsigned a;
    asm("{ .reg .u64 t; cvta.to.shared.u64 t, %1; cvt.u32.u64 %0, t; }" : "=r"(a) : "l"(p));
    return a;
}
#define CP16(dst, src) \
    asm volatile("cp.async.cg.shared.global [%0], [%1], 16;" :: "r"(dst), "l"(src))
#define CP_COMMIT() asm volatile("cp.async.commit_group;" ::: "memory")
#define CP_WAIT(n)  asm volatile("cp.async.wait_group %0;" :: "n"(n) : "memory")

#define LDSM4(R, addr)                                                       \
    asm volatile("ldmatrix.sync.aligned.m8n8.x4.shared.b16 {%0,%1,%2,%3}, [%4];" \
        : "=r"((R)[0]), "=r"((R)[1]), "=r"((R)[2]), "=r"((R)[3]) : "r"(addr))

#define MMA16816F16(C, A, B0, B1)                                            \
    asm volatile("mma.sync.aligned.m16n8k16.row.col.f32.f16.f16.f32 "        \
        "{%0,%1,%2,%3}, {%4,%5,%6,%7}, {%8,%9}, {%0,%1,%2,%3};"              \
        : "+f"((C)[0]), "+f"((C)[1]), "+f"((C)[2]), "+f"((C)[3])             \
        : "r"((A)[0]), "r"((A)[1]), "r"((A)[2]), "r"((A)[3]),                \
          "r"(B0), "r"(B1))

/* SW128 swizzle for 128-byte rows */
__device__ __forceinline__ unsigned swz128(unsigned off) { return off ^ ((off >> 3) & 0x70); }

/* ------------------------------------------------------------------ */
/* CSR build (dtype detect in k_zero; scan3 folded into consumers;    */
/* edge decode cached by k_hist)                                      */
/* ------------------------------------------------------------------ */
__global__ void k_zero(const void* et_raw) {
    int i = blockIdx.x * blockDim.x + threadIdx.x;
    if (i < NSEG) { g_seg_cnt[i] = 0; g_cursor[i] = 0; }
    if (i < 2) g_ticket[i] = 0;
    /* block 0: int64-vs-int32 detection on edge_type words */
    if (blockIdx.x == 0) {
        __shared__ int nz;
        if (threadIdx.x == 0) nz = 0;
        __syncthreads();
        const int* w = (const int*)et_raw;
        int cnt = 0;
        for (int j = threadIdx.x; j < 2048; j += blockDim.x)
            if (w[2 * j + 1] != 0) cnt++;
        atomicAdd(&nz, cnt);
        __syncthreads();
        if (threadIdx.x == 0) g_is64 = (nz == 0) ? 1 : 0;
    }
}

__device__ __forceinline__ void load_edge(const void* ei, const void* et, int e,
                                          int& src, int& dst, int& r) {
    if (g_is64) {
        const long long* p = (const long long*)ei;
        src = (int)p[e]; dst = (int)p[NE + e];
        r = (int)((const long long*)et)[e];
    } else {
        const int* p = (const int*)ei;
        src = p[e]; dst = p[NE + e];
        r = ((const int*)et)[e];
    }
}

/* histogram + decoded-edge cache (k_place reuses the decode) */
__global__ void k_hist(const void* ei, const void* et) {
    int e = blockIdx.x * blockDim.x + threadIdx.x;
    if (e >= NE) return;
    int s, d, r; load_edge(ei, et, e, s, d, r);
    int seg = d * NREL + r;
    g_eseg[e] = seg;
    g_esrc[e] = s;
    atomicAdd(&g_seg_cnt[seg], 1);
}

/* per-block exclusive scan; block totals to g_blk */
__global__ void k_scan1() {
    __shared__ int ws[8];
    int i = blockIdx.x * 256 + threadIdx.x;
    int lane = threadIdx.x & 31, w = threadIdx.x >> 5;
    int v = g_seg_cnt[i];
    int s = v;
#pragma unroll
    for (int d = 1; d < 32; d <<= 1) {
        int t = __shfl_up_sync(0xffffffffu, s, d);
        if (lane >= d) s += t;
    }
    if (lane == 31) ws[w] = s;
    __syncthreads();
    if (w == 0) {
        int val = (lane < 8) ? ws[lane] : 0;
        int sc = val;
#pragma unroll
        for (int d = 1; d < 8; d <<= 1) {
            int t = __shfl_up_sync(0xffffffffu, sc, d);
            if (lane >= d) sc += t;
        }
        if (lane < 8) ws[lane] = sc - val;
    }
    __syncthreads();
    int excl = s - v + ws[w];
    g_seg_off[i] = excl;                       /* partial: block-local */
    if (threadIdx.x == 255) g_blk[blockIdx.x] = excl + v;
}
__global__ void k_scan2() {
    __shared__ int sh[1024];
    int t = threadIdx.x;
    int v = (t < 625) ? g_blk[t] : 0;
    sh[t] = v;
    __syncthreads();
    for (int d = 1; d < 1024; d <<= 1) {
        int u = (t >= d) ? sh[t - d] : 0;
        __syncthreads();
        sh[t] += u;
        __syncthreads();
    }
    if (t < 625) g_blkpre[t] = sh[t] - v;
}

__global__ void k_place() {
    int e = blockIdx.x * blockDim.x + threadIdx.x;
    if (e >= NE) return;
    int seg = g_eseg[e];
    int base = g_seg_off[seg] + g_blkpre[seg >> 8];   /* scan3 folded in */
    g_sorted_src[base + atomicAdd(&g_cursor[seg], 1)] = g_esrc[e];
}

/* ------------------------------------------------------------------ */
/* operand preparation                                                */
/* ------------------------------------------------------------------ */
__global__ void k_convW(const float* __restrict__ W1, const float* __restrict__ root1,
                        __half* __restrict__ bh1,
                        const float* __restrict__ W2, const float* __restrict__ root2,
                        __half* __restrict__ bh2) {
    __shared__ float t[32][33];
    const float* W    = blockIdx.z ? W2 : W1;
    const float* root = blockIdx.z ? root2 : root1;
    __half* bh        = blockIdx.z ? bh2 : bh1;
    int tx = threadIdx.x, ty = threadIdx.y;
    int kb = blockIdx.x * 32, nb = blockIdx.y * 32;
    for (int j = ty; j < 32; j += 8) {
        int k = kb + j;
        const float* src = (k < KMEAN) ? (W + (size_t)k * DIN)
                                       : (root + (size_t)(k - KMEAN) * DIN);
        t[j][tx] = src[nb + tx];
    }
    __syncthreads();
    for (int j = ty; j < 32; j += 8) {
        int n = nb + j;
        bh[(size_t)n * KTOT + kb + tx] = __float2half_rn(t[tx][j]);
    }
}

__global__ void k_convX(const float* __restrict__ x, __half* __restrict__ h) {
    int idx = blockIdx.x * blockDim.x + threadIdx.x;
    if (idx >= NN * (DIN / 4)) return;
    float4 v = ((const float4*)x)[idx];
    __half2 a = __floats2half2_rn(v.x, v.y);
    __half2 b = __floats2half2_rn(v.z, v.w);
    ((__half2*)h)[idx * 2 + 0] = a;
    ((__half2*)h)[idx * 2 + 1] = b;
}

/* segment mean over fp16 rows -> fp16 mean region (fp32 accum).      */
/* meanH written with streaming hint (write-once 247 MB stream).      */
__global__ void k_aggregate(const __half* __restrict__ xin) {
    int gw = (blockIdx.x * blockDim.x + threadIdx.x) >> 5;
    if (gw >= NSEG) return;
    int lane = threadIdx.x & 31;
    int off = g_seg_off[gw] + g_blkpre[gw >> 8];   /* scan3 folded in */
    int cnt = g_seg_cnt[gw];

    float acc[24];
#pragma unroll
    for (int j = 0; j < 24; j++) acc[j] = 0.f;

    for (int e = 0; e < cnt; e++) {
        const uint4* row = (const uint4*)(xin + (size_t)g_sorted_src[off + e] * DIN);
#pragma unroll
        for (int j = 0; j < 3; j++) {
            uint4 v = row[j * 32 + lane];
            const __half2* h2 = (const __half2*)&v;
#pragma unroll
            for (int q = 0; q < 4; q++) {
                float2 f = __half22float2(h2[q]);
                acc[j * 8 + q * 2 + 0] += f.x;
                acc[j * 8 + q * 2 + 1] += f.y;
            }
        }
    }
    float inv = 1.0f / fmaxf((float)cnt, 1.0f);
    uint4* mh = (uint4*)(g_meanH + (size_t)gw * DIN);   /* gw*768 == dst*6144 + r*768 */
#pragma unroll
    for (int j = 0; j < 3; j++) {
        uint4 o;
        __half2* h2 = (__half2*)&o;
#pragma unroll
        for (int q = 0; q < 4; q++)
            h2[q] = __floats2half2_rn(acc[j * 8 + q * 2] * inv,
                                      acc[j * 8 + q * 2 + 1] * inv);
        __stcs(&mh[j * 32 + lane], o);          /* evict-first streaming store */
    }
}

/* ------------------------------------------------------------------ */
/* single-product fp16 GEMM via mma.sync — PERSISTENT CTAs            */
/* 296 CTAs (2/SM) dynamically claim 128x128 tiles via global ticket. */
/* Per tile: BK=64, 8 warps (2M x 4N), warp tile 64x32, multistage.   */
/* Mainloop is at its measured local optimum — DO NOT touch.          */
/* ------------------------------------------------------------------ */
#define STG_SZ   32768                      /* A 16K + B 16K */
#define OFF_A(b) ((b) * STG_SZ + 0)
#define OFF_B(b) ((b) * STG_SZ + 16384)
#define SMEM_TOTAL (3 * STG_SZ)             /* 98304 */

__global__ __launch_bounds__(256, 2)
void k_gemm_mma(const __half* __restrict__ meanH, const __half* __restrict__ tailH,
                const __half* __restrict__ BH,
                const float* __restrict__ bias, float* __restrict__ outF,
                __half* __restrict__ auxH,
                int do_relu, int write_f32, int write_f16, int ticket_id) {
    extern __shared__ __align__(1024) char smem[];
    __shared__ int s_tile;
    const int tid  = threadIdx.x;
    const int wid  = tid >> 5, lane = tid & 31;
    const int wm   = wid >> 2;          /* 0..1 : warp M tile (64 rows) */
    const int wn   = wid & 3;           /* 0..3 : warp N tile (32 cols) */
    const unsigned sbase = smem_u32(smem);
    const int lrow = lane & 15, lcol = lane >> 4;

    for (;;) {
        /* ---- claim a tile ----
         * Single barrier: publishes s_tile AND ensures the previous
         * tile's MMAs finished before prologue overwrites smem.       */
        if (tid == 0) s_tile = atomicAdd(&g_ticket[ticket_id], 1);
        __syncthreads();
        const int tile = s_tile;
        if (tile >= NTILES) return;
        const int n0 = (tile % NTILE_N) * 128;
        const int m0 = (tile / NTILE_N) * 128;

        float acc[4][4][4];
#pragma unroll
        for (int a = 0; a < 4; a++)
#pragma unroll
            for (int b = 0; b < 4; b++)
#pragma unroll
                for (int c = 0; c < 4; c++) acc[a][b][c] = 0.f;

        /* ---- stage loader: 8 cp.async(16B) per thread per stage ---- */
        auto issue_stage = [&](int s, int buf) {
            const int kc = s * 64;
            const __half* ah;
            size_t stride; int c0;
            if (kc < KMEAN) { ah = meanH; stride = KMEAN; c0 = kc; }
            else            { ah = tailH; stride = DIN;   c0 = kc - KMEAN; }
            /* A: 128 rows x 8 chunks of 16B */
#pragma unroll
            for (int t = 0; t < 4; t++) {
                int c   = tid + t * 256;             /* 0..1023 */
                int row = c >> 3, kg = c & 7;
                unsigned sw = swz128((unsigned)(row * 128 + kg * 16));
                int grow = m0 + row; if (grow >= NN) grow = NN - 1;  /* clamp pad rows */
                const char* sa = (const char*)(ah + (size_t)grow * stride + c0) + kg * 16;
                CP16(sbase + OFF_A(buf) + sw, sa);
            }
            /* B: 128 rows x 8 chunks of 16B */
#pragma unroll
            for (int t = 0; t < 4; t++) {
                int c   = tid + t * 256;
                int row = c >> 3, kg = c & 7;
                unsigned sw = swz128((unsigned)(row * 128 + kg * 16));
                const char* sb = (const char*)(BH + (size_t)(n0 + row) * KTOT + kc) + kg * 16;
                CP16(sbase + OFF_B(buf) + sw, sb);
            }
        };

        /* 2-stage prologue */
        issue_stage(0, 0); CP_COMMIT();
        issue_stage(1, 1); CP_COMMIT();

        int buf = 0;
        for (int s = 0; s < NSTG; s++) {
            CP_WAIT(1);
            __syncthreads();

            if (s + 2 < NSTG) issue_stage(s + 2, (s + 2) % 3);
            CP_COMMIT();

            unsigned baseA = sbase + OFF_A(buf);
            unsigned baseB = sbase + OFF_B(buf);

#pragma unroll
            for (int ks = 0; ks < 4; ks++) {
                unsigned bh[2][4];
#pragma unroll
                for (int p = 0; p < 2; p++) {
                    unsigned off = swz128((unsigned)((wn * 32 + p * 16 + lrow) * 128
                                                     + ks * 32 + lcol * 16));
                    LDSM4(bh[p], baseB + off);
                }
#pragma unroll
                for (int mb = 0; mb < 4; mb++) {
                    unsigned af[4];
                    unsigned off = swz128((unsigned)((wm * 64 + mb * 16 + lrow) * 128
                                                     + ks * 32 + lcol * 16));
                    LDSM4(af, baseA + off);
#pragma unroll
                    for (int nb = 0; nb < 4; nb++) {
                        int p = nb >> 1, q = nb & 1;
                        MMA16816F16(acc[mb][nb], af, bh[p][q], bh[p][q + 2]);
                    }
                }
            }
            buf = (buf == 2) ? 0 : buf + 1;
        }
        CP_WAIT(0);     /* drain trailing (empty) groups */

        /* ---- epilogue: bias (+ReLU); registers+gmem only, no smem ----
         * nb outer / mb inner so each bias pair is loaded exactly once.
         * fp32 final output: write-once -> streaming store.
         * fp16 aux (h): re-read by next layer's gather -> cached store. */
#pragma unroll
        for (int nb = 0; nb < 4; nb++) {
            int col = n0 + wn * 32 + nb * 8 + (lane & 3) * 2;
            float bv0 = __ldg(&bias[col]);
            float bv1 = __ldg(&bias[col + 1]);
#pragma unroll
            for (int mb = 0; mb < 4; mb++) {
                int rbase = m0 + wm * 64 + mb * 16 + (lane >> 2);
#pragma unroll
                for (int h = 0; h < 2; h++) {
                    int row = rbase + h * 8;
                    float v0 = acc[mb][nb][h * 2 + 0] + bv0;
                    float v1 = acc[mb][nb][h * 2 + 1] + bv1;
                    if (do_relu) { v0 = fmaxf(v0, 0.f); v1 = fmaxf(v1, 0.f); }
                    if (row < NN) {
                        size_t e = (size_t)row * DIN + col;
                        if (write_f32)
                            __stcs((float2*)&outF[e], make_float2(v0, v1));
                        if (write_f16) {
                            __half2 hv = __floats2half2_rn(v0, v1);
                            *(__half2*)(auxH + e) = hv;
                        }
                    }
                }
            }
        }
    }
}

/* ------------------------------------------------------------------ */
extern "C" void kernel_launch(void* const* d_in, const int* in_sizes, int n_in,
                              void* d_out, int out_size) {
    const float* x     = (const float*)d_in[0];
    const void*  ei    = d_in[1];
    const void*  et    = d_in[2];
    const float* W1    = (const float*)d_in[3];
    const float* root1 = (const float*)d_in[4];
    const float* b1    = (const float*)d_in[5];
    const float* W2    = (const float*)d_in[6];
    const float* root2 = (const float*)d_in[7];
    const float* b2    = (const float*)d_in[8];
    float*       out   = (float*)d_out;

    __half *meanH, *tailH, *BH;
    cudaGetSymbolAddress((void**)&meanH, g_meanH);
    cudaGetSymbolAddress((void**)&tailH, g_tailH);
    cudaGetSymbolAddress((void**)&BH, g_BH);
    __half* tail1H = tailH + (size_t)MPAD * DIN;
    __half* B2H    = BH + (size_t)DIN * KTOT;

    cudaFuncSetAttribute(k_gemm_mma, cudaFuncAttributeMaxDynamicSharedMemorySize, SMEM_TOTAL);

    /* CSR build (shared by both layers) */
    k_zero<<<(NSEG + 255) / 256, 256>>>(et);
    k_hist<<<(NE + 255) / 256, 256>>>(ei, et);
    k_scan1<<<NSEG / 256, 256>>>();
    k_scan2<<<1, 1024>>>();
    k_place<<<(NE + 255) / 256, 256>>>();

    /* operand prep (both W conversions in one launch) */
    dim3 wgrid(KTOT / 32, DIN / 32, 2);
    k_convW<<<wgrid, dim3(32, 8)>>>(W1, root1, BH, W2, root2, B2H);
    k_convX<<<(NN * (DIN / 4) + 255) / 256, 256>>>(x, tailH);

    /* layer 1: aggregate fp16 x -> mean; GEMM -> fp16 h only */
    k_aggregate<<<NSEG / 8, 256>>>(tailH);
    k_gemm_mma<<<NPERS, 256, SMEM_TOTAL>>>(meanH, tailH, BH, b1,
                                           nullptr, tail1H, 1, 0, 1, 0);
    /* layer 2: aggregate fp16 h -> mean; GEMM -> fp32 out */
    k_aggregate<<<NSEG / 8, 256>>>(tail1H);
    k_gemm_mma<<<NPERS, 256, SMEM_TOTAL>>>(meanH, tail1H, B2H, b2,
                                           out, nullptr, 0, 1, 0, 1);
}